// round 16
// baseline (speedup 1.0000x reference)
#include <cuda_runtime.h>
#include <cuda_bf16.h>
#include <cstdint>

#define Bdim 256
#define Ddim 128
#define Cdim 8000
#define CPAD 8064
#define SCALE_F 64.0f
#define MARGIN_F 0.5f
#define EPS_F 1e-12f
#define NCTA_Y 63     // consumer CTAs per y-block; barrier scope is per-y
#define NTHR 512

// ---------------- device scratch (no allocations allowed) ----------------
__device__ uint4 g_neHi4[Bdim * 16];   // row = b, 16 x 16B of bf16 along k
__device__ uint4 g_neLo4[Bdim * 16];
__device__ uint4 g_grHi4[Bdim * 16];
__device__ float g_s[Bdim];
__device__ float g_rowsum[Bdim];
__device__ int g_countY[2];            // per-y barrier counters

// ---------------- warp-MMA helpers (family-safe: ldmatrix + mma.sync) -------
__device__ __forceinline__ uint32_t smem_u32(const void* p) {
    uint32_t a;
    asm("{ .reg .u64 t; cvta.to.shared.u64 t, %1; cvt.u32.u64 %0, t; }"
        : "=r"(a) : "l"(p));
    return a;
}
__device__ __forceinline__ void ldsm_x4(uint32_t& r0, uint32_t& r1,
                                        uint32_t& r2, uint32_t& r3,
                                        uint32_t addr) {
    asm volatile(
        "ldmatrix.sync.aligned.m8n8.x4.shared.b16 {%0,%1,%2,%3}, [%4];"
        : "=r"(r0), "=r"(r1), "=r"(r2), "=r"(r3) : "r"(addr));
}
__device__ __forceinline__ void mma16816(float* d, const uint32_t* a,
                                         const uint32_t* b) {
    asm volatile(
        "mma.sync.aligned.m16n8k16.row.col.f32.bf16.bf16.f32 "
        "{%0,%1,%2,%3}, {%4,%5,%6,%7}, {%8,%9}, {%0,%1,%2,%3};"
        : "+f"(d[0]), "+f"(d[1]), "+f"(d[2]), "+f"(d[3])
        : "r"(a[0]), "r"(a[1]), "r"(a[2]), "r"(a[3]), "r"(b[0]), "r"(b[1]));
}
__device__ __forceinline__ uint32_t bf16pair(float v0, float v1) {
    __nv_bfloat16 h0 = __float2bfloat16(v0);
    __nv_bfloat16 h1 = __float2bfloat16(v1);
    return (uint32_t)__bfloat16_as_ushort(h0) |
           ((uint32_t)__bfloat16_as_ushort(h1) << 16);
}

// smem tile geometry: 128 rows x 136 bf16 (272B rows -> 4-bank shift per row)
#define ROW_U4 17
#define TILE_U4 (128 * ROW_U4)           // 2176 uint4 = 34816 B
// layout: 0 neHi, 1 neLo, 2 grHi, 3 nwHi, 4 nwLo  (5 tiles = 174080 B)

// ---------------- K2: normalize embds, gather+normalize gr, splits, s[b] ----
__global__ void k_prep(const float* __restrict__ embds,
                       const float* __restrict__ w,
                       const int* __restrict__ labels) {
    int b = blockIdx.x;
    int d = threadIdx.x;  // 128 threads
    __shared__ float redA[4];
    __shared__ float redC[4];
    __shared__ float redB[4];

    float e = embds[b * Ddim + d];
    int lb = labels[b];
    float wv = w[d * Cdim + lb];

    float v = e * e;
    float ww = wv * wv;
#pragma unroll
    for (int o = 16; o > 0; o >>= 1) {
        v += __shfl_xor_sync(0xffffffffu, v, o);
        ww += __shfl_xor_sync(0xffffffffu, ww, o);
    }
    if ((d & 31) == 0) { redA[d >> 5] = v; redC[d >> 5] = ww; }
    __syncthreads();
    float ss = redA[0] + redA[1] + redA[2] + redA[3];
    float ss2 = redC[0] + redC[1] + redC[2] + redC[3];
    float ne = e * rsqrtf(fmaxf(ss, EPS_F));
    float gr = wv * rsqrtf(fmaxf(ss2, EPS_F));

    __nv_bfloat16 neh = __float2bfloat16(ne);
    __nv_bfloat16 nel = __float2bfloat16(ne - __bfloat162float(neh));
    __nv_bfloat16 grh = __float2bfloat16(gr);
    ((unsigned short*)g_neHi4)[b * 128 + d] = __bfloat16_as_ushort(neh);
    ((unsigned short*)g_neLo4)[b * 128 + d] = __bfloat16_as_ushort(nel);
    ((unsigned short*)g_grHi4)[b * 128 + d] = __bfloat16_as_ushort(grh);

    float sv = ne * gr;
#pragma unroll
    for (int o = 16; o > 0; o >>= 1) sv += __shfl_xor_sync(0xffffffffu, sv, o);
    if ((d & 31) == 0) redB[d >> 5] = sv;
    __syncthreads();
    if (d == 0) {
        g_s[b] = redB[0] + redB[1] + redB[2] + redB[3];
        g_rowsum[b] = 0.f;
        if (b == 0) { g_countY[0] = 0; g_countY[1] = 0; }
    }
}

// ---------------- K3: fused w-normalize/split + dual GEMM + softmax ---------
// 512 threads (16 warps); smem 170KB -> 1 CTA/SM; 126 CTAs all co-resident.
__global__ __launch_bounds__(NTHR, 1) void k_main(float* __restrict__ out,
                                                  const float* __restrict__ w,
                                                  const int* __restrict__ labels) {
    extern __shared__ uint4 smem4[];
    __shared__ float red2[NTHR];
    __shared__ float sinv[128];
    __shared__ float sRow[128];    // per-CTA rowsum accumulator, then 1/rowsum
    __shared__ float sS[128];      // g_s for this b-block
    __shared__ int sLb[128];       // labels for this b-block
    const int tid = threadIdx.x;
    const int wid = tid >> 5;
    const int lane = tid & 31;
    const int cBase = blockIdx.x * 128;
    const int yb = blockIdx.y;
    const int bBase = yb * 128;

    // ---- load w column chunk straight into registers ----
    const int c = tid & 127;
    const int kq = tid >> 7;            // 0..3
    float wv[32];
    {
        int cCol = cBase + c;
        if (cCol < Cdim) {
            const float* wp = w + (size_t)(kq * 32) * Cdim + cCol;
#pragma unroll
            for (int i = 0; i < 32; i++) wv[i] = wp[(size_t)i * Cdim];
        } else {
#pragma unroll
            for (int i = 0; i < 32; i++) wv[i] = 0.f;
        }
    }

    // ---- stage ne/gr tiles (independent of the w loads above) ----
    {
        const uint4* srcs[3] = {g_neHi4 + bBase * 16, g_neLo4 + bBase * 16,
                                g_grHi4 + bBase * 16};
#pragma unroll
        for (int t3 = 0; t3 < 3; t3++) {
            const uint4* src = srcs[t3];
            uint4* dst = smem4 + t3 * TILE_U4;
#pragma unroll
            for (int i = 0; i < 4; i++) {
                int idx = tid + i * NTHR;
                dst[(idx >> 4) * ROW_U4 + (idx & 15)] = src[idx];
            }
        }
    }
    if (tid < 128) {
        sS[tid] = g_s[bBase + tid];
        sLb[tid] = labels[bBase + tid];
        sRow[tid] = 0.f;
    }

    // ---- column norm partials from registers ----
    {
        float ss = 0.f;
#pragma unroll
        for (int i = 0; i < 32; i++) ss = fmaf(wv[i], wv[i], ss);
        red2[tid] = ss;
    }
    __syncthreads();   // red2 ready + ne/gr tiles staged
    if (tid < 128) {
        sinv[tid] = rsqrtf(fmaxf(red2[tid] + red2[tid + 128] +
                                 red2[tid + 256] + red2[tid + 384], EPS_F));
    }
    __syncthreads();

    // ---- convert registers -> bf16 hi/lo nw tiles (MMA layout) ----
    {
        float inv = sinv[c];
        uint4* nwHi = smem4 + 3 * TILE_U4;
        uint4* nwLo = smem4 + 4 * TILE_U4;
#pragma unroll
        for (int q = 0; q < 4; q++) {       // 4 16B k-units of 8 bf16
            uint32_t hi[4], lo[4];
#pragma unroll
            for (int uu = 0; uu < 4; uu++) {
                float v0 = wv[q * 8 + uu * 2 + 0] * inv;
                float v1 = wv[q * 8 + uu * 2 + 1] * inv;
                __nv_bfloat16 h0 = __float2bfloat16(v0);
                __nv_bfloat16 h1 = __float2bfloat16(v1);
                hi[uu] = (uint32_t)__bfloat16_as_ushort(h0) |
                         ((uint32_t)__bfloat16_as_ushort(h1) << 16);
                lo[uu] = bf16pair(v0 - __bfloat162float(h0),
                                  v1 - __bfloat162float(h1));
            }
            int kunit = kq * 4 + q;
            nwHi[c * ROW_U4 + kunit] = make_uint4(hi[0], hi[1], hi[2], hi[3]);
            nwLo[c * ROW_U4 + kunit] = make_uint4(lo[0], lo[1], lo[2], lo[3]);
        }
    }
    __syncthreads();

    const uint32_t sb0 = smem_u32(smem4);
    const int m0 = (wid >> 2) * 32;          // warp m-range (b), 4 groups
    const int n0 = (wid & 3) * 32;           // warp n-range (c), 4 groups
    const int rowA = (lane & 7) + ((lane >> 3) & 1) * 8;
    const int uA = lane >> 4;
    const int rowB = (lane & 7) + (lane >> 4) * 8;
    const int uB = (lane >> 3) & 1;

    float accC[2][4][4];
    float accG[2][4][4];
#pragma unroll
    for (int mt = 0; mt < 2; mt++)
#pragma unroll
        for (int j = 0; j < 4; j++)
#pragma unroll
            for (int r = 0; r < 4; r++) { accC[mt][j][r] = 0.f; accG[mt][j][r] = 0.f; }

    // ks-outer loop. cos: 3 split passes (hi*hi, lo*hi, hi*lo). G: hi*hi only
    // (G feeds only rsqrt(2-2G); penalty error < 2e-4 absolute, 5x under gate).
    const uint32_t baseNeHi = sb0;
    const uint32_t baseNeLo = sb0 + (uint32_t)(1 * TILE_U4 * 16);
    const uint32_t baseGrHi = sb0 + (uint32_t)(2 * TILE_U4 * 16);
    const uint32_t baseBHi  = sb0 + (uint32_t)(3 * TILE_U4 * 16);
    const uint32_t baseBLo  = sb0 + (uint32_t)(4 * TILE_U4 * 16);
#pragma unroll
    for (int ks = 0; ks < 8; ks++) {
        uint32_t bfH[4][2], bfL[4][2];
#pragma unroll
        for (int jp = 0; jp < 2; jp++) {
            uint32_t boff =
                (uint32_t)(((n0 + jp * 16 + rowB) * ROW_U4 + ks * 2 + uB) * 16);
            ldsm_x4(bfH[2 * jp][0], bfH[2 * jp][1],
                    bfH[2 * jp + 1][0], bfH[2 * jp + 1][1], baseBHi + boff);
            ldsm_x4(bfL[2 * jp][0], bfL[2 * jp][1],
                    bfL[2 * jp + 1][0], bfL[2 * jp + 1][1], baseBLo + boff);
        }
#pragma unroll
        for (int mt = 0; mt < 2; mt++) {
            uint32_t aoff =
                (uint32_t)(((m0 + mt * 16 + rowA) * ROW_U4 + ks * 2 + uA) * 16);
            uint32_t anH[4], anL[4], agH[4];
            ldsm_x4(anH[0], anH[1], anH[2], anH[3], baseNeHi + aoff);
            ldsm_x4(anL[0], anL[1], anL[2], anL[3], baseNeLo + aoff);
            ldsm_x4(agH[0], agH[1], agH[2], agH[3], baseGrHi + aoff);
#pragma unroll
            for (int j = 0; j < 4; j++) {
                mma16816(accC[mt][j], anH, bfH[j]);
                mma16816(accG[mt][j], agH, bfH[j]);
                mma16816(accC[mt][j], anL, bfH[j]);
                mma16816(accC[mt][j], anH, bfL[j]);
            }
        }
    }

    // ---- epilogue part 1: penalties + exp (kept in accC) + smem rowsums ----
    float* out_logit = out;
    float* out_pen = out + (size_t)Bdim * Cdim;
#pragma unroll
    for (int mt = 0; mt < 2; mt++) {
#pragma unroll
        for (int h = 0; h < 2; h++) {
            int row = m0 + mt * 16 + h * 8 + (lane >> 2);
            int b = bBase + row;
            float sbv = sS[row];
            int lb = sLb[row];
            float esum = 0.f;
#pragma unroll
            for (int j = 0; j < 4; j++) {
                int c0 = cBase + n0 + j * 8 + (lane & 3) * 2;
                if (c0 < Cdim) {   // Cdim even, c0 even -> pair fully valid
                    float cv0 = accC[mt][j][h * 2 + 0];
                    float cv1 = accC[mt][j][h * 2 + 1];
                    float g0 = accG[mt][j][h * 2 + 0];
                    float g1 = accG[mt][j][h * 2 + 1];
                    float w0 = (sbv - cv0) * rsqrtf(fmaxf(2.f - 2.f * g0, EPS_F));
                    float w1 = (sbv - cv1) * rsqrtf(fmaxf(2.f - 2.f * g1, EPS_F));
                    if (c0 == lb) w0 = 0.f;       // dw == 0 exactly in reference
                    if (c0 + 1 == lb) w1 = 0.f;
                    float p0 = MARGIN_F - fminf(MARGIN_F, w0);
                    float p1 = MARGIN_F - fminf(MARGIN_F, w1);
                    float e0 = __expf(SCALE_F * cv0 - SCALE_F);
                    float e1 = __expf(SCALE_F * cv1 - SCALE_F);
                    accC[mt][j][h * 2 + 0] = e0;   // stash ev in registers
                    accC[mt][j][h * 2 + 1] = e1;
                    esum += e0 + e1;
                    *(float2*)&out_pen[(size_t)b * Cdim + c0] = make_float2(p0, p1);
                }
            }
            esum += __shfl_xor_sync(0xffffffffu, esum, 1);
            esum += __shfl_xor_sync(0xffffffffu, esum, 2);
            if ((lane & 3) == 0) atomicAdd(&sRow[row], esum);
        }
    }
    __syncthreads();

    // ---- one global atomic per b per CTA, then PER-Y grid barrier ----
    // A CTA's b-rows live entirely in its y-block; it only needs the 63
    // same-y CTAs' contributions. Waiting on 63 instead of 126 halves the
    // skew population and decouples the two y-groups' release times.
    if (tid < 128) atomicAdd(&g_rowsum[bBase + tid], sRow[tid]);
    __threadfence();
    __syncthreads();
    if (tid == 0) {
        atomicAdd(&g_countY[yb], 1);
        while (*(volatile int*)&g_countY[yb] < NCTA_Y) { }
    }
    __syncthreads();
    if (tid < 128) sRow[tid] = 1.f / __ldcg(&g_rowsum[bBase + tid]);
    __syncthreads();

    // ---- epilogue part 2: scaled logits ----
#pragma unroll
    for (int mt = 0; mt < 2; mt++) {
#pragma unroll
        for (int h = 0; h < 2; h++) {
            int row = m0 + mt * 16 + h * 8 + (lane >> 2);
            int b = bBase + row;
            float inv = sRow[row];
#pragma unroll
            for (int j = 0; j < 4; j++) {
                int c0 = cBase + n0 + j * 8 + (lane & 3) * 2;
                if (c0 < Cdim) {
                    float e0 = accC[mt][j][h * 2 + 0] * inv;
                    float e1 = accC[mt][j][h * 2 + 1] * inv;
                    *(float2*)&out_logit[(size_t)b * Cdim + c0] =
                        make_float2(e0, e1);
                }
            }
        }
    }
}

// ---------------- launch ----------------
extern "C" void kernel_launch(void* const* d_in, const int* in_sizes, int n_in,
                              void* d_out, int out_size) {
    const float* embds = (const float*)d_in[0];   // [256,128]
    const float* w     = (const float*)d_in[1];   // [128,8000]
    const int* labels  = (const int*)d_in[2];     // [256]
    float* out = (float*)d_out;                   // logits then penalties

    const int kMainSmem = 5 * TILE_U4 * 16;       // 174080 B
    cudaFuncSetAttribute(k_main, cudaFuncAttributeMaxDynamicSharedMemorySize,
                         kMainSmem);

    k_prep<<<Bdim, Ddim>>>(embds, w, labels);

    dim3 g3(CPAD / 128, 2);                       // (63, 2) = 126 CTAs
    k_main<<<g3, NTHR, kMainSmem>>>(out, w, labels);
}

// round 17
// speedup vs baseline: 1.1067x; 1.1067x over previous
#include <cuda_runtime.h>
#include <cuda_bf16.h>
#include <cstdint>

#define Bdim 256
#define Ddim 128
#define Cdim 8000
#define CPAD 8064
#define SCALE_F 64.0f
#define MARGIN_F 0.5f
#define EPS_F 1e-12f
#define NCTA_Y 63     // consumer CTAs per y-block; barrier scope is per-y
#define NTHR 512

// ---------------- device scratch (no allocations allowed) ----------------
__device__ uint4 g_neHi4[Bdim * 16];   // row = b, 16 x 16B of bf16 along k
__device__ uint4 g_neLo4[Bdim * 16];
__device__ uint4 g_grHi4[Bdim * 16];
__device__ float g_s[Bdim];
__device__ float g_rowsum[Bdim];
__device__ int g_countY[2];            // per-y barrier counters

// ---------------- helpers (family-safe) ----------------
__device__ __forceinline__ uint32_t smem_u32(const void* p) {
    uint32_t a;
    asm("{ .reg .u64 t; cvta.to.shared.u64 t, %1; cvt.u32.u64 %0, t; }"
        : "=r"(a) : "l"(p));
    return a;
}
__device__ __forceinline__ void ldsm_x4(uint32_t& r0, uint32_t& r1,
                                        uint32_t& r2, uint32_t& r3,
                                        uint32_t addr) {
    asm volatile(
        "ldmatrix.sync.aligned.m8n8.x4.shared.b16 {%0,%1,%2,%3}, [%4];"
        : "=r"(r0), "=r"(r1), "=r"(r2), "=r"(r3) : "r"(addr));
}
__device__ __forceinline__ void mma16816(float* d, const uint32_t* a,
                                         const uint32_t* b) {
    asm volatile(
        "mma.sync.aligned.m16n8k16.row.col.f32.bf16.bf16.f32 "
        "{%0,%1,%2,%3}, {%4,%5,%6,%7}, {%8,%9}, {%0,%1,%2,%3};"
        : "+f"(d[0]), "+f"(d[1]), "+f"(d[2]), "+f"(d[3])
        : "r"(a[0]), "r"(a[1]), "r"(a[2]), "r"(a[3]), "r"(b[0]), "r"(b[1]));
}
__device__ __forceinline__ uint32_t bf16pair(float v0, float v1) {
    __nv_bfloat16 h0 = __float2bfloat16(v0);
    __nv_bfloat16 h1 = __float2bfloat16(v1);
    return (uint32_t)__bfloat16_as_ushort(h0) |
           ((uint32_t)__bfloat16_as_ushort(h1) << 16);
}

// smem tile geometry: 128 rows x 136 bf16 (272B rows -> 4-bank shift per row)
#define ROW_U4 17
#define TILE_U4 (128 * ROW_U4)           // 2176 uint4 = 34816 B
// layout: 0 neHi, 1 neLo, 2 grHi, 3 nwHi, 4 nwLo  (5 tiles = 174080 B)

// ---------------- K2: normalize embds, gather+normalize gr, splits, s[b] ----
__global__ void k_prep(const float* __restrict__ embds,
                       const float* __restrict__ w,
                       const int* __restrict__ labels) {
    // PDL: allow the dependent k_main grid to launch now; it will
    // griddepcontrol.wait before touching any of this kernel's outputs.
    asm volatile("griddepcontrol.launch_dependents;");

    int b = blockIdx.x;
    int d = threadIdx.x;  // 128 threads
    __shared__ float redA[4];
    __shared__ float redC[4];
    __shared__ float redB[4];

    float e = embds[b * Ddim + d];
    int lb = labels[b];
    float wv = w[d * Cdim + lb];

    float v = e * e;
    float ww = wv * wv;
#pragma unroll
    for (int o = 16; o > 0; o >>= 1) {
        v += __shfl_xor_sync(0xffffffffu, v, o);
        ww += __shfl_xor_sync(0xffffffffu, ww, o);
    }
    if ((d & 31) == 0) { redA[d >> 5] = v; redC[d >> 5] = ww; }
    __syncthreads();
    float ss = redA[0] + redA[1] + redA[2] + redA[3];
    float ss2 = redC[0] + redC[1] + redC[2] + redC[3];
    float ne = e * rsqrtf(fmaxf(ss, EPS_F));
    float gr = wv * rsqrtf(fmaxf(ss2, EPS_F));

    __nv_bfloat16 neh = __float2bfloat16(ne);
    __nv_bfloat16 nel = __float2bfloat16(ne - __bfloat162float(neh));
    __nv_bfloat16 grh = __float2bfloat16(gr);
    ((unsigned short*)g_neHi4)[b * 128 + d] = __bfloat16_as_ushort(neh);
    ((unsigned short*)g_neLo4)[b * 128 + d] = __bfloat16_as_ushort(nel);
    ((unsigned short*)g_grHi4)[b * 128 + d] = __bfloat16_as_ushort(grh);

    float sv = ne * gr;
#pragma unroll
    for (int o = 16; o > 0; o >>= 1) sv += __shfl_xor_sync(0xffffffffu, sv, o);
    if ((d & 31) == 0) redB[d >> 5] = sv;
    __syncthreads();
    if (d == 0) {
        g_s[b] = redB[0] + redB[1] + redB[2] + redB[3];
        g_rowsum[b] = 0.f;
        if (b == 0) { g_countY[0] = 0; g_countY[1] = 0; }
    }
}

// ---------------- K3: fused w-normalize/split + dual GEMM + softmax ---------
// 512 threads (16 warps); smem 170KB -> 1 CTA/SM; 126 CTAs all co-resident.
// Launched with PDL: starts during k_prep, waits only before ne/gr staging.
__global__ __launch_bounds__(NTHR, 1) void k_main(float* __restrict__ out,
                                                  const float* __restrict__ w,
                                                  const int* __restrict__ labels) {
    extern __shared__ uint4 smem4[];
    __shared__ float red2[NTHR];
    __shared__ float sinv[128];
    __shared__ float sRow[128];    // per-CTA rowsum accumulator, then 1/rowsum
    __shared__ float sS[128];      // g_s for this b-block
    __shared__ int sLb[128];       // labels for this b-block
    const int tid = threadIdx.x;
    const int wid = tid >> 5;
    const int lane = tid & 31;
    const int cBase = blockIdx.x * 128;
    const int yb = blockIdx.y;
    const int bBase = yb * 128;

    // ---- load w column chunk straight into registers (prep-independent) ----
    const int c = tid & 127;
    const int kq = tid >> 7;            // 0..3
    float wv[32];
    {
        int cCol = cBase + c;
        if (cCol < Cdim) {
            const float* wp = w + (size_t)(kq * 32) * Cdim + cCol;
#pragma unroll
            for (int i = 0; i < 32; i++) wv[i] = wp[(size_t)i * Cdim];
        } else {
#pragma unroll
            for (int i = 0; i < 32; i++) wv[i] = 0.f;
        }
    }

    // ---- column norm partials from registers ----
    {
        float ss = 0.f;
#pragma unroll
        for (int i = 0; i < 32; i++) ss = fmaf(wv[i], wv[i], ss);
        red2[tid] = ss;
    }
    __syncthreads();
    if (tid < 128) {
        sinv[tid] = rsqrtf(fmaxf(red2[tid] + red2[tid + 128] +
                                 red2[tid + 256] + red2[tid + 384], EPS_F));
        sRow[tid] = 0.f;
    }
    __syncthreads();

    // ---- convert registers -> bf16 hi/lo nw tiles (MMA layout) ----
    {
        float inv = sinv[c];
        uint4* nwHi = smem4 + 3 * TILE_U4;
        uint4* nwLo = smem4 + 4 * TILE_U4;
#pragma unroll
        for (int q = 0; q < 4; q++) {       // 4 16B k-units of 8 bf16
            uint32_t hi[4], lo[4];
#pragma unroll
            for (int uu = 0; uu < 4; uu++) {
                float v0 = wv[q * 8 + uu * 2 + 0] * inv;
                float v1 = wv[q * 8 + uu * 2 + 1] * inv;
                __nv_bfloat16 h0 = __float2bfloat16(v0);
                __nv_bfloat16 h1 = __float2bfloat16(v1);
                hi[uu] = (uint32_t)__bfloat16_as_ushort(h0) |
                         ((uint32_t)__bfloat16_as_ushort(h1) << 16);
                lo[uu] = bf16pair(v0 - __bfloat162float(h0),
                                  v1 - __bfloat162float(h1));
            }
            int kunit = kq * 4 + q;
            nwHi[c * ROW_U4 + kunit] = make_uint4(hi[0], hi[1], hi[2], hi[3]);
            nwLo[c * ROW_U4 + kunit] = make_uint4(lo[0], lo[1], lo[2], lo[3]);
        }
    }

    // ---- PDL: wait for k_prep completion (memory flushed), then stage ----
    asm volatile("griddepcontrol.wait;" ::: "memory");
    {
        const uint4* srcs[3] = {g_neHi4 + bBase * 16, g_neLo4 + bBase * 16,
                                g_grHi4 + bBase * 16};
#pragma unroll
        for (int t3 = 0; t3 < 3; t3++) {
            const uint4* src = srcs[t3];
            uint4* dst = smem4 + t3 * TILE_U4;
#pragma unroll
            for (int i = 0; i < 4; i++) {
                int idx = tid + i * NTHR;
                dst[(idx >> 4) * ROW_U4 + (idx & 15)] = src[idx];
            }
        }
    }
    if (tid < 128) {
        sS[tid] = g_s[bBase + tid];
        sLb[tid] = labels[bBase + tid];
    }
    __syncthreads();

    const uint32_t sb0 = smem_u32(smem4);
    const int m0 = (wid >> 2) * 32;          // warp m-range (b), 4 groups
    const int n0 = (wid & 3) * 32;           // warp n-range (c), 4 groups
    const int rowA = (lane & 7) + ((lane >> 3) & 1) * 8;
    const int uA = lane >> 4;
    const int rowB = (lane & 7) + (lane >> 4) * 8;
    const int uB = (lane >> 3) & 1;

    float accC[2][4][4];
    float accG[2][4][4];
#pragma unroll
    for (int mt = 0; mt < 2; mt++)
#pragma unroll
        for (int j = 0; j < 4; j++)
#pragma unroll
            for (int r = 0; r < 4; r++) { accC[mt][j][r] = 0.f; accG[mt][j][r] = 0.f; }

    // ks-outer loop. cos: 3 split passes (hi*hi, lo*hi, hi*lo). G: hi*hi only
    // (G feeds only rsqrt(2-2G); penalty error < 2e-4 absolute, 5x under gate).
    const uint32_t baseNeHi = sb0;
    const uint32_t baseNeLo = sb0 + (uint32_t)(1 * TILE_U4 * 16);
    const uint32_t baseGrHi = sb0 + (uint32_t)(2 * TILE_U4 * 16);
    const uint32_t baseBHi  = sb0 + (uint32_t)(3 * TILE_U4 * 16);
    const uint32_t baseBLo  = sb0 + (uint32_t)(4 * TILE_U4 * 16);
#pragma unroll
    for (int ks = 0; ks < 8; ks++) {
        uint32_t bfH[4][2], bfL[4][2];
#pragma unroll
        for (int jp = 0; jp < 2; jp++) {
            uint32_t boff =
                (uint32_t)(((n0 + jp * 16 + rowB) * ROW_U4 + ks * 2 + uB) * 16);
            ldsm_x4(bfH[2 * jp][0], bfH[2 * jp][1],
                    bfH[2 * jp + 1][0], bfH[2 * jp + 1][1], baseBHi + boff);
            ldsm_x4(bfL[2 * jp][0], bfL[2 * jp][1],
                    bfL[2 * jp + 1][0], bfL[2 * jp + 1][1], baseBLo + boff);
        }
#pragma unroll
        for (int mt = 0; mt < 2; mt++) {
            uint32_t aoff =
                (uint32_t)(((m0 + mt * 16 + rowA) * ROW_U4 + ks * 2 + uA) * 16);
            uint32_t anH[4], anL[4], agH[4];
            ldsm_x4(anH[0], anH[1], anH[2], anH[3], baseNeHi + aoff);
            ldsm_x4(anL[0], anL[1], anL[2], anL[3], baseNeLo + aoff);
            ldsm_x4(agH[0], agH[1], agH[2], agH[3], baseGrHi + aoff);
#pragma unroll
            for (int j = 0; j < 4; j++) {
                mma16816(accC[mt][j], anH, bfH[j]);
                mma16816(accG[mt][j], agH, bfH[j]);
                mma16816(accC[mt][j], anL, bfH[j]);
                mma16816(accC[mt][j], anH, bfL[j]);
            }
        }
    }

    // ---- epilogue part 1: penalties + exp (kept in accC) + smem rowsums ----
    float* out_logit = out;
    float* out_pen = out + (size_t)Bdim * Cdim;
#pragma unroll
    for (int mt = 0; mt < 2; mt++) {
#pragma unroll
        for (int h = 0; h < 2; h++) {
            int row = m0 + mt * 16 + h * 8 + (lane >> 2);
            int b = bBase + row;
            float sbv = sS[row];
            int lb = sLb[row];
            float esum = 0.f;
#pragma unroll
            for (int j = 0; j < 4; j++) {
                int c0 = cBase + n0 + j * 8 + (lane & 3) * 2;
                if (c0 < Cdim) {   // Cdim even, c0 even -> pair fully valid
                    float cv0 = accC[mt][j][h * 2 + 0];
                    float cv1 = accC[mt][j][h * 2 + 1];
                    float g0 = accG[mt][j][h * 2 + 0];
                    float g1 = accG[mt][j][h * 2 + 1];
                    float w0 = (sbv - cv0) * rsqrtf(fmaxf(2.f - 2.f * g0, EPS_F));
                    float w1 = (sbv - cv1) * rsqrtf(fmaxf(2.f - 2.f * g1, EPS_F));
                    if (c0 == lb) w0 = 0.f;       // dw == 0 exactly in reference
                    if (c0 + 1 == lb) w1 = 0.f;
                    float p0 = MARGIN_F - fminf(MARGIN_F, w0);
                    float p1 = MARGIN_F - fminf(MARGIN_F, w1);
                    float e0 = __expf(SCALE_F * cv0 - SCALE_F);
                    float e1 = __expf(SCALE_F * cv1 - SCALE_F);
                    accC[mt][j][h * 2 + 0] = e0;   // stash ev in registers
                    accC[mt][j][h * 2 + 1] = e1;
                    esum += e0 + e1;
                    *(float2*)&out_pen[(size_t)b * Cdim + c0] = make_float2(p0, p1);
                }
            }
            esum += __shfl_xor_sync(0xffffffffu, esum, 1);
            esum += __shfl_xor_sync(0xffffffffu, esum, 2);
            if ((lane & 3) == 0) atomicAdd(&sRow[row], esum);
        }
    }
    __syncthreads();

    // ---- one global atomic per b per CTA, then PER-Y grid barrier ----
    if (tid < 128) atomicAdd(&g_rowsum[bBase + tid], sRow[tid]);
    __threadfence();
    __syncthreads();
    if (tid == 0) {
        atomicAdd(&g_countY[yb], 1);
        while (*(volatile int*)&g_countY[yb] < NCTA_Y) { }
    }
    __syncthreads();
    if (tid < 128) sRow[tid] = 1.f / __ldcg(&g_rowsum[bBase + tid]);
    __syncthreads();

    // ---- epilogue part 2: scaled logits ----
#pragma unroll
    for (int mt = 0; mt < 2; mt++) {
#pragma unroll
        for (int h = 0; h < 2; h++) {
            int row = m0 + mt * 16 + h * 8 + (lane >> 2);
            int b = bBase + row;
            float inv = sRow[row];
#pragma unroll
            for (int j = 0; j < 4; j++) {
                int c0 = cBase + n0 + j * 8 + (lane & 3) * 2;
                if (c0 < Cdim) {
                    float e0 = accC[mt][j][h * 2 + 0] * inv;
                    float e1 = accC[mt][j][h * 2 + 1] * inv;
                    *(float2*)&out_logit[(size_t)b * Cdim + c0] =
                        make_float2(e0, e1);
                }
            }
        }
    }
}

// ---------------- launch ----------------
extern "C" void kernel_launch(void* const* d_in, const int* in_sizes, int n_in,
                              void* d_out, int out_size) {
    const float* embds = (const float*)d_in[0];   // [256,128]
    const float* w     = (const float*)d_in[1];   // [128,8000]
    const int* labels  = (const int*)d_in[2];     // [256]
    float* out = (float*)d_out;                   // logits then penalties

    const int kMainSmem = 5 * TILE_U4 * 16;       // 174080 B
    cudaFuncSetAttribute(k_main, cudaFuncAttributeMaxDynamicSharedMemorySize,
                         kMainSmem);

    k_prep<<<Bdim, Ddim>>>(embds, w, labels);

    // k_main with programmatic dependent launch: overlaps its w-prologue with
    // k_prep; griddepcontrol.wait inside orders the dependent reads.
    cudaLaunchConfig_t cfg = {};
    cfg.gridDim = dim3(CPAD / 128, 2);            // (63, 2) = 126 CTAs
    cfg.blockDim = dim3(NTHR);
    cfg.dynamicSmemBytes = kMainSmem;
    cfg.stream = 0;
    cudaLaunchAttribute attr[1];
    attr[0].id = cudaLaunchAttributeProgrammaticStreamSerialization;
    attr[0].val.programmaticStreamSerializationAllowed = 1;
    cfg.attrs = attr;
    cfg.numAttrs = 1;
    cudaLaunchKernelEx(&cfg, k_main, out, (const float*)w, (const int*)labels);
}